// round 2
// baseline (speedup 1.0000x reference)
#include <cuda_runtime.h>
#include <cuda_bf16.h>

// SIR SDE simulator: B=8192 independent trajectories, 4900 Euler-Maruyama steps
// (steps 4900..4999 never affect the output slice), sampled every 100 steps (49 samples),
// then per-trajectory features: max, (argmax+u)/49, std(diff(log x)).
//
// Design: 1 trajectory per thread, 256 blocks x 32 threads (one warp per SMSP, max spread
// since only 256 warps of work exist). dW is streamed with a 20-deep register prefetch
// ring so DRAM latency is hidden behind the per-step dependent-FP chain.

#define BSZ   8192
#define PF    20          // prefetch depth (steps ahead); 100 % PF == 0 required
#define NSAMP 49

__global__ __launch_bounds__(32, 1)
void sir_sde_kernel(const float* __restrict__ cond,
                    const float* __restrict__ dW,
                    const float* __restrict__ u,
                    float* __restrict__ out)
{
    const int b = blockIdx.x * blockDim.x + threadIdx.x;
    if (b >= BSZ) return;

    // ---- per-trajectory parameters ----
    const float inf_rate = cond[b * 4 + 0];
    const float rec      = cond[b * 4 + 1];
    const float mr       = cond[b * 4 + 2];
    const float vol      = cond[b * 4 + 3];

    const float DT      = 0.01f;
    const float r0_init = __fdiv_rn(inf_rate, rec);
    const float sdt     = sqrtf(DT);          // matches jnp.sqrt(0.01f)
    const float dtmr    = DT * mr;            // same value reference recomputes each step

    // ---- state (r never feeds back into s/i/r0 and is not an output: dropped) ----
    float s    = 0.99f;
    float icur = 0.01f;
    float r0   = r0_init;

    // ---- feature accumulators ----
    float cur_max = -3.402823466e38f;
    int   cur_arg = 0;
    float prev_lg = 0.0f;
    float sumd = 0.0f, sumd2 = 0.0f;

    // ---- dW prefetch ring: buf[k] always holds dW for the next steps in order ----
    const float* pw = dW + b;                 // step t lives at pw[t * BSZ]
    float buf[PF];
#pragma unroll
    for (int k = 0; k < PF; ++k) buf[k] = pw[k * BSZ];
    const float* pl = pw + (size_t)PF * BSZ;  // next load address (PF steps ahead)

    for (int j = 0; j < NSAMP; ++j) {
#pragma unroll 1
        for (int c = 0; c < 100 / PF; ++c) {
#pragma unroll
            for (int k = 0; k < PF; ++k) {
                const float dw = buf[k];
                buf[k] = pl[k * BSZ];         // refill PF steps ahead (max idx 4919 < 5000)

                // Euler-Maruyama step (reference operation order; all old-state reads)
                const float ni = r0 * rec * s;            // newly_infected
                const float nr = rec * icur;              // newly_recovered
                const float sn = s - DT * ni;
                const float in_ = icur + DT * (ni - nr);
                float sq;
                asm("sqrt.approx.f32 %0, %1;" : "=f"(sq) : "f"(fabsf(r0)));
                const float rn = r0 + dtmr * (r0_init - r0) + sq * vol * (dw * sdt);

                s = sn; icur = in_; r0 = rn;
            }
            pl += (size_t)PF * BSZ;
        }

        // ---- sample after steps 99, 199, ..., 4899 ----
        float x = icur;
        // nan_to_num(nan=0, posinf=0, neginf=0); bit test is fast-math safe
        if ((__float_as_uint(x) & 0x7f800000u) == 0x7f800000u) x = 0.0f;
        x = fmaxf(x, 1e-5f);                  // clip lower bound

        if (x > cur_max) { cur_max = x; cur_arg = j; }  // first-occurrence argmax
        const float lg = logf(x);
        if (j > 0) {
            const float d = lg - prev_lg;
            sumd  += d;
            sumd2 += d * d;
        }
        prev_lg = lg;
    }

    // ---- features ----
    const float max_at = ((float)cur_arg + u[b]) / 49.0f;
    const float mean   = sumd * (1.0f / 48.0f);
    float var = sumd2 * (1.0f / 48.0f) - mean * mean;   // ddof=0
    var = fmaxf(var, 0.0f);
    const float volf = sqrtf(var);

    out[b * 3 + 0] = cur_max;
    out[b * 3 + 1] = max_at;
    out[b * 3 + 2] = volf;
}

extern "C" void kernel_launch(void* const* d_in, const int* in_sizes, int n_in,
                              void* d_out, int out_size)
{
    const float* cond = (const float*)d_in[0];   // (8192, 4)
    const float* dW   = (const float*)d_in[1];   // (5000, 8192)
    const float* u    = (const float*)d_in[2];   // (8192,)
    float* out        = (float*)d_out;           // (8192, 3)

    sir_sde_kernel<<<BSZ / 32, 32>>>(cond, dW, u, out);
}

// round 4
// speedup vs baseline: 1.4734x; 1.4734x over previous
#include <cuda_runtime.h>
#include <cuda_bf16.h>
#include <cstdint>

// SIR SDE: 8192 trajectories x 4900 effective steps, sampled every 100 steps (49 samples),
// then per-trajectory features: max, (argmax+u)/49, std(diff(log x)).
//
// R4: same design as R3 (cp.async 3-buffer smem pipeline + shortened r0 chain) with the
// tail-drain bug fixed: the last two iterations have <2 pending cp.async groups, so they
// must use wait_group<0> (full drain) — wait_group<1> returned before the final chunk
// landed, causing racy reads of the last 20 steps (sample j=48) and nondeterminism.

#define BSZ    8192
#define CH     20            // steps per chunk; 100 % CH == 0
#define NCHUNK 245           // 4900 effective steps
#define NSAMP  49

__device__ __forceinline__ void cp_async16(uint32_t saddr, const void* gptr) {
    asm volatile("cp.async.ca.shared.global [%0], [%1], 16;" :: "r"(saddr), "l"(gptr));
}
__device__ __forceinline__ void cp_commit() {
    asm volatile("cp.async.commit_group;");
}
template <int N>
__device__ __forceinline__ void cp_wait() {
    asm volatile("cp.async.wait_group %0;" :: "n"(N));
}

__global__ __launch_bounds__(32, 1)
void sir_sde_kernel(const float* __restrict__ cond,
                    const float* __restrict__ dW,
                    const float* __restrict__ u,
                    float* __restrict__ out)
{
    __shared__ float sdw[3 * CH * 32];      // 3 buffers x 20 steps x 32 lanes = 7.5 KB

    const int tid = threadIdx.x;
    const int b0  = blockIdx.x * 32;        // first trajectory of this block
    const int b   = b0 + tid;

    // ---------- per-trajectory parameters ----------
    const float inf_rate = cond[b * 4 + 0];
    const float rec      = cond[b * 4 + 1];
    const float mr       = cond[b * 4 + 2];
    const float vol      = cond[b * 4 + 3];

    const float DT      = 0.01f;
    const float r0_init = __fdiv_rn(inf_rate, rec);
    const float sdt     = sqrtf(DT);
    const float dtmr    = DT * mr;
    const float om      = 1.0f - dtmr;      // r0' = om*r0 + c1 + sqrt(|r0|)*c2
    const float c1      = dtmr * r0_init;
    const float kvol    = vol * sdt;

    // ---------- state ----------
    float s    = 0.99f;
    float icur = 0.01f;
    float r0   = r0_init;

    // ---------- feature accumulators ----------
    float cur_max = -3.402823466e38f;
    int   cur_arg = 0;
    float prev_lg = 0.0f;
    float sumd = 0.0f, sumd2 = 0.0f;

    // ---------- cp.async chunk copier ----------
    // chunk c covers gmem rows [c*CH, c*CH+CH); row r is 128 B at dW + (row*BSZ + b0).
    // flat smem buffer = CH rows x 128 B = 2560 B; thread copies 5 x 16 B.
    uint32_t smem_base;
    asm("{ .reg .u64 t; cvta.to.shared.u64 t, %1; cvt.u32.u64 %0, t; }"
        : "=r"(smem_base) : "l"(sdw));

    const char* gbase = (const char*)(dW + b0);

    auto issue_chunk = [&](int c, int bufidx) {
        const char* g = gbase + (size_t)c * CH * BSZ * 4;
        uint32_t sb = smem_base + bufidx * (CH * 128);
#pragma unroll
        for (int i = 0; i < 5; ++i) {
            int f   = i * 512 + tid * 16;       // flat byte offset in buffer
            int row = f >> 7;                   // /128
            int col = f & 127;
            cp_async16(sb + f, g + (size_t)row * BSZ * 4 + col);
        }
        cp_commit();
    };

    // prologue: chunks 0,1 in flight
    issue_chunk(0, 0);
    issue_chunk(1, 1);

    const float* sbuf = sdw;

#pragma unroll 1
    for (int c = 0; c < NCHUNK; ++c) {
        // Pending groups here are {c, c+1} except in the tail where no new chunks were
        // issued: there only {c} (or {c, c+1} at c==NCHUNK-2) remain, and wait<1> would
        // NOT guarantee chunk c completion. Fully drain for the last two iterations.
        if (c >= NCHUNK - 2) cp_wait<0>();
        else                 cp_wait<1>();
        __syncwarp();

        // burst-copy chunk c to registers (conflict-free LDS, all latencies overlap)
        float dwv[CH];
        const float* sp = sbuf + (c % 3) * (CH * 32) + tid;
#pragma unroll
        for (int k = 0; k < CH; ++k) dwv[k] = sp[k * 32];

        // refill: chunk c+2 goes into buffer (c+2)%3 (last touched by chunk c-1, long done)
        if (c + 2 < NCHUNK) issue_chunk(c + 2, (c + 2) % 3);

        // ---------- 20 Euler-Maruyama steps ----------
#pragma unroll
        for (int k = 0; k < CH; ++k) {
            const float c2 = dwv[k] * kvol;     // off the critical chain
            const float rr = r0 * rec;          // parallel with MUFU
            float sq;
            asm("sqrt.approx.f32 %0, %1;" : "=f"(sq) : "f"(fabsf(r0)));
            const float t  = fmaf(r0, om, c1);
            const float rn = fmaf(sq, c2, t);   // chain: MUFU(16) + FFMA(4)

            const float ni = rr * s;
            const float nr = rec * icur;
            const float sn = fmaf(ni, -DT, s);
            const float in_ = fmaf(DT, ni - nr, icur);

            s = sn; icur = in_; r0 = rn;
        }

        // ---------- sample after steps 99, 199, ..., 4899 ----------
        if (c % 5 == 4) {
            const int j = c / 5;
            float x = icur;
            if ((__float_as_uint(x) & 0x7f800000u) == 0x7f800000u) x = 0.0f; // nan/inf -> 0
            x = fmaxf(x, 1e-5f);

            if (x > cur_max) { cur_max = x; cur_arg = j; }
            const float lg = logf(x);
            if (j > 0) {
                const float d = lg - prev_lg;
                sumd  += d;
                sumd2 += d * d;
            }
            prev_lg = lg;
        }
    }

    // ---------- features ----------
    const float max_at = ((float)cur_arg + u[b]) / 49.0f;
    const float mean   = sumd * (1.0f / 48.0f);
    float var = sumd2 * (1.0f / 48.0f) - mean * mean;   // ddof=0
    var = fmaxf(var, 0.0f);

    out[b * 3 + 0] = cur_max;
    out[b * 3 + 1] = max_at;
    out[b * 3 + 2] = sqrtf(var);
}

extern "C" void kernel_launch(void* const* d_in, const int* in_sizes, int n_in,
                              void* d_out, int out_size)
{
    const float* cond = (const float*)d_in[0];   // (8192, 4)
    const float* dW   = (const float*)d_in[1];   // (5000, 8192)
    const float* u    = (const float*)d_in[2];   // (8192,)
    float* out        = (float*)d_out;           // (8192, 3)

    sir_sde_kernel<<<BSZ / 32, 32>>>(cond, dW, u, out);
}

// round 5
// speedup vs baseline: 1.4954x; 1.0149x over previous
#include <cuda_runtime.h>
#include <cuda_bf16.h>
#include <cstdint>

// SIR SDE: 8192 trajectories x 4900 effective steps, sampled every 100 steps (49 samples),
// features: max, (argmax+u)/49, std(diff(log x)).
//
// R5: geometry + issue-count fix.
//  - 128 blocks x 64 threads: <=1 block/SM, warps map to SMSP 0/1 -> every warp owns a
//    private SMSP (R4's 256x32 put two wid-0 warps on the SAME SMSP on 108 SMs -> 2x issue
//    serialization on the critical SMs).
//  - s eliminated via q = rec*s (only i is sampled; s only feeds ni = r0*q). Per-step
//    fma-pipe ops drop 11 -> ~8, leaving the MUFU(16)+FFMA(4) r0 chain as the limiter.
//  - dW streamed per-warp via cp.async 3-buffer smem pipeline (unchanged from R4, incl.
//    full drain on the last two chunks).

#define BSZ    8192
#define CH     20            // steps per chunk; 100 % CH == 0
#define NCHUNK 245           // 4900 effective steps
#define WPB    2             // warps per block
#define THREADS (WPB * 32)

__device__ __forceinline__ void cp_async16(uint32_t saddr, const void* gptr) {
    asm volatile("cp.async.ca.shared.global [%0], [%1], 16;" :: "r"(saddr), "l"(gptr));
}
__device__ __forceinline__ void cp_commit() {
    asm volatile("cp.async.commit_group;");
}
template <int N>
__device__ __forceinline__ void cp_wait() {
    asm volatile("cp.async.wait_group %0;" :: "n"(N));
}

__global__ __launch_bounds__(THREADS, 1)
void sir_sde_kernel(const float* __restrict__ cond,
                    const float* __restrict__ dW,
                    const float* __restrict__ u,
                    float* __restrict__ out)
{
    __shared__ float sdw[WPB][3 * CH * 32];   // per-warp: 3 bufs x 20 steps x 32 lanes

    const int lane = threadIdx.x & 31;
    const int w    = threadIdx.x >> 5;
    const int b0   = blockIdx.x * THREADS + w * 32;   // first trajectory of this warp
    const int b    = b0 + lane;

    // ---------- per-trajectory parameters ----------
    const float inf_rate = cond[b * 4 + 0];
    const float rec      = cond[b * 4 + 1];
    const float mr       = cond[b * 4 + 2];
    const float vol      = cond[b * 4 + 3];

    const float DT      = 0.01f;
    const float r0_init = __fdiv_rn(inf_rate, rec);
    const float sdt     = sqrtf(DT);
    const float dtmr    = DT * mr;
    const float om      = 1.0f - dtmr;        // r0' = om*r0 + c1 + sqrt(|r0|)*c2
    const float c1      = dtmr * r0_init;
    const float kvol    = vol * sdt;
    const float ndtrec  = -DT * rec;          // q' = q + ndtrec*ni
    const float omr     = 1.0f + ndtrec;      // i' = DT*ni + omr*i

    // ---------- state (s replaced by q = rec*s) ----------
    float q    = rec * 0.99f;
    float icur = 0.01f;
    float r0   = r0_init;

    // ---------- feature accumulators ----------
    float cur_max = -3.402823466e38f;
    int   cur_arg = 0;
    float prev_lg = 0.0f;
    float sumd = 0.0f, sumd2 = 0.0f;

    // ---------- cp.async chunk copier (per warp, self-contained) ----------
    uint32_t smem_base;
    asm("{ .reg .u64 t; cvta.to.shared.u64 t, %1; cvt.u32.u64 %0, t; }"
        : "=r"(smem_base) : "l"(&sdw[w][0]));

    const char* gbase = (const char*)(dW + b0);

    auto issue_chunk = [&](int c, int bufidx) {
        const char* g = gbase + (size_t)c * CH * BSZ * 4;
        uint32_t sb = smem_base + bufidx * (CH * 128);
#pragma unroll
        for (int i = 0; i < 5; ++i) {
            int f   = i * 512 + lane * 16;      // flat byte offset in this warp's buffer
            int row = f >> 7;                   // /128
            int col = f & 127;
            cp_async16(sb + f, g + (size_t)row * BSZ * 4 + col);
        }
        cp_commit();
    };

    // prologue: chunks 0,1 in flight
    issue_chunk(0, 0);
    issue_chunk(1, 1);

    const float* sbuf = &sdw[w][0];

#pragma unroll 1
    for (int c = 0; c < NCHUNK; ++c) {
        // Tail: fewer than 2 groups pending -> wait<1> would not cover chunk c. Full drain.
        if (c >= NCHUNK - 2) cp_wait<0>();
        else                 cp_wait<1>();
        __syncwarp();

        // burst-copy chunk c to registers (conflict-free LDS)
        float dwv[CH];
        const float* sp = sbuf + (c % 3) * (CH * 32) + lane;
#pragma unroll
        for (int k = 0; k < CH; ++k) dwv[k] = sp[k * 32];

        // refill chunk c+2 into buffer (c+2)%3 (last consumer finished a chunk ago)
        if (c + 2 < NCHUNK) issue_chunk(c + 2, (c + 2) % 3);

        // ---------- 20 Euler-Maruyama steps ----------
#pragma unroll
        for (int k = 0; k < CH; ++k) {
            const float c2 = dwv[k] * kvol;     // off the critical chain
            const float ni = r0 * q;            // newly_infected (= r0*rec*s)
            float sq;
            asm("sqrt.approx.f32 %0, %1;" : "=f"(sq) : "f"(fabsf(r0)));
            const float t   = fmaf(r0, om, c1);
            const float rn  = fmaf(sq, c2, t);  // chain: MUFU(16) + FFMA(4)
            const float qn  = fmaf(ni, ndtrec, q);
            const float in_ = fmaf(DT, ni, icur * omr);

            r0 = rn; q = qn; icur = in_;
        }

        // ---------- sample after steps 99, 199, ..., 4899 ----------
        if (c % 5 == 4) {
            const int j = c / 5;
            float x = icur;
            if ((__float_as_uint(x) & 0x7f800000u) == 0x7f800000u) x = 0.0f; // nan/inf -> 0
            x = fmaxf(x, 1e-5f);

            if (x > cur_max) { cur_max = x; cur_arg = j; }
            const float lg = logf(x);
            if (j > 0) {
                const float d = lg - prev_lg;
                sumd  += d;
                sumd2 += d * d;
            }
            prev_lg = lg;
        }
    }

    // ---------- features ----------
    const float max_at = ((float)cur_arg + u[b]) / 49.0f;
    const float mean   = sumd * (1.0f / 48.0f);
    float var = sumd2 * (1.0f / 48.0f) - mean * mean;   // ddof=0
    var = fmaxf(var, 0.0f);

    out[b * 3 + 0] = cur_max;
    out[b * 3 + 1] = max_at;
    out[b * 3 + 2] = sqrtf(var);
}

extern "C" void kernel_launch(void* const* d_in, const int* in_sizes, int n_in,
                              void* d_out, int out_size)
{
    const float* cond = (const float*)d_in[0];   // (8192, 4)
    const float* dW   = (const float*)d_in[1];   // (5000, 8192)
    const float* u    = (const float*)d_in[2];   // (8192,)
    float* out        = (float*)d_out;           // (8192, 3)

    sir_sde_kernel<<<BSZ / THREADS, THREADS>>>(cond, dW, u, out);
}